// round 1
// baseline (speedup 1.0000x reference)
#include <cuda_runtime.h>
#include <cstdint>

#define B_   32
#define N_   64
#define GS_  80
#define NG_  6400
#define NA_  3
#define TK_  3
#define NC_  80

// output layout (floats), reference return order: bboxes, scores, anc, fg
#define BB_OFF  0
#define SC_OFF  (B_*NA_*NG_*4)                 // 2,457,600
#define ANC_OFF (SC_OFF + B_*NA_*NG_*NC_)      // 51,609,600
#define FG_OFF  (ANC_OFF + 6)                  // 51,609,606

// scratch (device globals — no allocation allowed)
__device__ int g_top3[B_ * N_ * TK_];
__device__ int g_asgn[B_ * NG_];   // packed: tgt(8) | label<<8 | fg<<16

typedef unsigned long long ull;

__device__ __forceinline__ void merge3(ull* a, const ull* b) {
#pragma unroll
    for (int j = 0; j < 3; j++) {
        ull k = b[j];
        if (k < a[2]) {
            if (k < a[0])      { a[2] = a[1]; a[1] = a[0]; a[0] = k; }
            else if (k < a[1]) { a[2] = a[1]; a[1] = k; }
            else               { a[2] = k; }
        }
    }
}

// ---------------- Kernel A: top-3 nearest cells per (b, gt) ----------------
__global__ void topk_kernel(const float* __restrict__ gt_cxys) {
    const int bn = blockIdx.x;                 // b*N_ + gt
    const float cx = gt_cxys[bn * 2 + 0];
    const float cy = gt_cxys[bn * 2 + 1];

    ull k0 = ~0ull, k1 = ~0ull, k2 = ~0ull;
    for (int g = threadIdx.x; g < NG_; g += blockDim.x) {
        const int x = g % GS_, y = g / GS_;
        const float d = fabsf(((float)x + 0.5f) - cx) + fabsf(((float)y + 0.5f) - cy);
        const ull key = ((ull)__float_as_uint(d) << 32) | (unsigned)g;
        if (key < k2) {
            if (key < k0)      { k2 = k1; k1 = k0; k0 = key; }
            else if (key < k1) { k2 = k1; k1 = key; }
            else               { k2 = key; }
        }
    }

    __shared__ ull sk[128][3];
    sk[threadIdx.x][0] = k0; sk[threadIdx.x][1] = k1; sk[threadIdx.x][2] = k2;
    __syncthreads();
#pragma unroll
    for (int s = 64; s > 0; s >>= 1) {
        if (threadIdx.x < s) merge3(sk[threadIdx.x], sk[threadIdx.x + s]);
        __syncthreads();
    }
    if (threadIdx.x < TK_)
        g_top3[bn * TK_ + threadIdx.x] = (int)(sk[0][threadIdx.x] & 0xffffffffu);
}

// ------------- Kernel B: per-(b,g) claim resolution -> tgt/label/fg -------------
__global__ void assign_kernel(const float* __restrict__ gt_cxys,
                              const float* __restrict__ mask_gt,
                              const int*   __restrict__ gt_labels) {
    const int b = blockIdx.y;
    const int g = blockIdx.x * blockDim.x + threadIdx.x;   // gridDim.x=25, blockDim=256

    __shared__ float scx[N_], scy[N_];
    __shared__ int   st[N_ * TK_];
    if (threadIdx.x < N_) {
        scx[threadIdx.x] = gt_cxys[(b * N_ + threadIdx.x) * 2 + 0];
        scy[threadIdx.x] = gt_cxys[(b * N_ + threadIdx.x) * 2 + 1];
    }
    if (threadIdx.x < N_ * TK_)
        st[threadIdx.x] = g_top3[b * N_ * TK_ + threadIdx.x];
    __syncthreads();
    if (g >= NG_) return;

    const float* mg = mask_gt + (size_t)b * N_ * NG_ + g;

    int count = 0, first = -1;
#pragma unroll 4
    for (int t = 0; t < N_; t++) {
        const bool mem = (st[t*3] == g) | (st[t*3+1] == g) | (st[t*3+2] == g);
        if (mem) {
            if (mg[(size_t)t * NG_] != 0.0f) { count++; if (first < 0) first = t; }
        }
    }

    int tgt, fg;
    if (count > 1) {
        const float fx = (float)(g % GS_) + 0.5f;
        const float fy = (float)(g / GS_) + 0.5f;
        ull best = ~0ull;
        for (int t = 0; t < N_; t++) {
            const float d = fabsf(fx - scx[t]) + fabsf(fy - scy[t]);
            const ull key = ((ull)__float_as_uint(d) << 32) | (unsigned)t;
            best = key < best ? key : best;
        }
        const int mgt = (int)(best & 0xffffffffu);
        const bool mem = (st[mgt*3] == g) | (st[mgt*3+1] == g) | (st[mgt*3+2] == g);
        const bool has = mem && (mg[(size_t)mgt * NG_] != 0.0f);
        fg  = has ? 1 : 0;
        tgt = has ? mgt : 0;
    } else {
        fg  = count;
        tgt = (count == 1) ? first : 0;
    }
    const int lab = gt_labels[b * N_ + tgt];
    g_asgn[b * NG_ + g] = tgt | (lab << 8) | (fg << 16);
}

// ------------- Kernel C: bboxes (float4), fg mask, anc copy -------------
__global__ void box_kernel(const float* __restrict__ anc_wh,
                           const float* __restrict__ grid,
                           const float* __restrict__ gt_cxys,
                           const float* __restrict__ gt_whs,
                           float* __restrict__ out) {
    const int idx = blockIdx.x * blockDim.x + threadIdx.x;   // B*NA*NG = 614400
    if (idx >= B_ * NA_ * NG_) return;
    const int g = idx % NG_;
    const int a = (idx / NG_) % NA_;
    const int b = idx / (NG_ * NA_);

    const int packed = g_asgn[b * NG_ + g];
    const int tgt = packed & 0xff;
    const int fg  = (packed >> 16) & 1;

    const float cx = gt_cxys[(b * N_ + tgt) * 2 + 0];
    const float cy = gt_cxys[(b * N_ + tgt) * 2 + 1];
    const float w  = gt_whs [(b * N_ + tgt) * 2 + 0];
    const float h  = gt_whs [(b * N_ + tgt) * 2 + 1];
    const float gx = grid[g * 2 + 0];
    const float gy = grid[g * 2 + 1];

    reinterpret_cast<float4*>(out + BB_OFF)[idx] = make_float4(cx - gx, cy - gy, w, h);

    const float aw = anc_wh[a * 2 + 0], ah = anc_wh[a * 2 + 1];
    const float r1 = w / aw, r2 = h / ah;
    const float m  = fmaxf(fmaxf(r1, 1.0f / r1), fmaxf(r2, 1.0f / r2));
    out[FG_OFF + idx] = (fg && (m < 4.0f)) ? 1.0f : 0.0f;

    if (idx < 6) out[ANC_OFF + idx] = anc_wh[idx];
}

// ------------- Kernel D: one-hot scores, one float4 per thread -------------
__global__ void score_kernel(float* __restrict__ out) {
    const long long idx = (long long)blockIdx.x * blockDim.x + threadIdx.x;
    const long long total = (long long)B_ * NA_ * NG_ * (NC_ / 4);     // 12,288,000
    if (idx >= total) return;

    const int c4 = (int)(idx % (NC_ / 4));
    const long long q = idx / (NC_ / 4);        // (b,a,g) flat
    const int g = (int)(q % NG_);
    const int b = (int)(q / (NG_ * NA_));

    const int lab = (g_asgn[b * NG_ + g] >> 8) & 0xff;
    const int c = c4 * 4;
    float4 v;
    v.x = (c + 0 == lab) ? 1.0f : 0.0f;
    v.y = (c + 1 == lab) ? 1.0f : 0.0f;
    v.z = (c + 2 == lab) ? 1.0f : 0.0f;
    v.w = (c + 3 == lab) ? 1.0f : 0.0f;
    reinterpret_cast<float4*>(out + SC_OFF)[idx] = v;
}

extern "C" void kernel_launch(void* const* d_in, const int* in_sizes, int n_in,
                              void* d_out, int out_size) {
    const float* anc_wh    = (const float*)d_in[0];
    const float* grid      = (const float*)d_in[1];
    const int*   gt_labels = (const int*)  d_in[2];
    const float* gt_cxys   = (const float*)d_in[3];
    const float* gt_whs    = (const float*)d_in[4];
    const float* mask_gt   = (const float*)d_in[5];
    float* out = (float*)d_out;

    topk_kernel<<<B_ * N_, 128>>>(gt_cxys);

    dim3 gb(NG_ / 256, B_);
    assign_kernel<<<gb, 256>>>(gt_cxys, mask_gt, gt_labels);

    const int nbox = B_ * NA_ * NG_;
    box_kernel<<<(nbox + 255) / 256, 256>>>(anc_wh, grid, gt_cxys, gt_whs, out);

    const long long nsc = (long long)B_ * NA_ * NG_ * (NC_ / 4);
    score_kernel<<<(unsigned)((nsc + 255) / 256), 256>>>(out);
}

// round 2
// speedup vs baseline: 1.6799x; 1.6799x over previous
#include <cuda_runtime.h>
#include <cstdint>

#define B_   32
#define N_   64
#define GS_  80
#define NG_  6400
#define NA_  3
#define TK_  3
#define NC_  80

// output layout (floats), reference return order: bboxes, scores, anc, fg
#define BB_OFF  0
#define SC_OFF  (B_*NA_*NG_*4)                 // 2,457,600
#define ANC_OFF (SC_OFF + B_*NA_*NG_*NC_)      // 51,609,600
#define FG_OFF  (ANC_OFF + 6)                  // 51,609,606

// scratch (device globals — no allocation allowed)
__device__ int g_top3[B_ * N_ * TK_];
__device__ int g_asgn[B_ * NG_];   // packed: tgt(8) | label<<8 | fg<<16

typedef unsigned long long ull;

// ---------------- Kernel A: top-3 nearest cells per (b, gt) -----------------
// One THREAD per GT. The 3 smallest L1 distances (and any exact-tie partners
// relevant to set membership) provably lie within the 7x7 cell window centered
// on floor(cx),floor(cy): 3rd-best dist <= 2.0 everywhere (incl. borders), so
// any candidate has |dx|,|dy| <= 2.0  =>  x in [cx-2.5, cx+2.5] subset of
// [floor(cx)-3, floor(cx)+3]. 49 candidates per thread, key = (distbits<<32)|g
// min-select reproduces top_k's lowest-index tie-break exactly.
__global__ void topk_kernel(const float* __restrict__ gt_cxys) {
    const int bn = blockIdx.x * blockDim.x + threadIdx.x;
    if (bn >= B_ * N_) return;
    const float cx = gt_cxys[bn * 2 + 0];
    const float cy = gt_cxys[bn * 2 + 1];

    int xs = (int)floorf(cx) - 3; xs = xs < 0 ? 0 : (xs > GS_ - 7 ? GS_ - 7 : xs);
    int ys = (int)floorf(cy) - 3; ys = ys < 0 ? 0 : (ys > GS_ - 7 ? GS_ - 7 : ys);

    ull k0 = ~0ull, k1 = ~0ull, k2 = ~0ull;
#pragma unroll
    for (int dy = 0; dy < 7; dy++) {
        const int y = ys + dy;
        const float ady = fabsf(((float)y + 0.5f) - cy);
#pragma unroll
        for (int dx = 0; dx < 7; dx++) {
            const int x = xs + dx;
            const float d = fabsf(((float)x + 0.5f) - cx) + ady;
            const ull key = ((ull)__float_as_uint(d) << 32) | (unsigned)(y * GS_ + x);
            if (key < k2) {
                if (key < k0)      { k2 = k1; k1 = k0; k0 = key; }
                else if (key < k1) { k2 = k1; k1 = key; }
                else               { k2 = key; }
            }
        }
    }
    g_top3[bn * TK_ + 0] = (int)(k0 & 0xffffffffu);
    g_top3[bn * TK_ + 1] = (int)(k1 & 0xffffffffu);
    g_top3[bn * TK_ + 2] = (int)(k2 & 0xffffffffu);
}

// ------------- Kernel B: scatter claims, resolve -> tgt/label/fg -------------
// One block per batch. 192 claims scattered via smem atomicAdd; per-cell
// resolution is O(1) except rare multi-claim conflicts (argmin over 64 GTs).
__global__ void assign_kernel(const float* __restrict__ gt_cxys,
                              const float* __restrict__ mask_gt,
                              const int*   __restrict__ gt_labels) {
    const int b   = blockIdx.x;
    const int tid = threadIdx.x;   // blockDim = 256

    __shared__ int   claims[NG_];            // (count<<16) + sum_of_t
    __shared__ float scx[N_], scy[N_];
    __shared__ int   st[N_ * TK_];
    __shared__ int   slab[N_];

    for (int g = tid; g < NG_; g += 256) claims[g] = 0;
    if (tid < N_) {
        scx[tid]  = gt_cxys[(b * N_ + tid) * 2 + 0];
        scy[tid]  = gt_cxys[(b * N_ + tid) * 2 + 1];
        slab[tid] = gt_labels[b * N_ + tid];
    }
    if (tid < N_ * TK_) st[tid] = g_top3[b * N_ * TK_ + tid];
    __syncthreads();

    if (tid < N_ * TK_) {
        const int t = tid / TK_;
        const int g = st[tid];
        const float v = mask_gt[((size_t)(b * N_ + t)) * NG_ + g];
        if (v != 0.0f) atomicAdd(&claims[g], (1 << 16) + t);
    }
    __syncthreads();

    for (int g = tid; g < NG_; g += 256) {
        const int c   = claims[g];
        const int cnt = c >> 16;
        int tgt, fg;
        if (cnt == 0)      { tgt = 0;           fg = 0; }
        else if (cnt == 1) { tgt = c & 0xffff;  fg = 1; }
        else {
            // conflict: nearest GT over ALL 64 (ties -> lowest t), keep only
            // if that GT itself claims g (topk) AND is valid
            const float fx = (float)(g % GS_) + 0.5f;
            const float fy = (float)(g / GS_) + 0.5f;
            ull best = ~0ull;
            for (int t = 0; t < N_; t++) {
                const float d = fabsf(fx - scx[t]) + fabsf(fy - scy[t]);
                const ull key = ((ull)__float_as_uint(d) << 32) | (unsigned)t;
                best = key < best ? key : best;
            }
            const int mgt = (int)(best & 0xffffffffu);
            const bool mem = (st[mgt*3] == g) | (st[mgt*3+1] == g) | (st[mgt*3+2] == g);
            const bool has = mem && (mask_gt[((size_t)(b * N_ + mgt)) * NG_ + g] != 0.0f);
            fg  = has ? 1 : 0;
            tgt = has ? mgt : 0;
        }
        g_asgn[b * NG_ + g] = tgt | (slab[tgt] << 8) | (fg << 16);
    }
}

// ------------- Kernel C: bboxes (float4), fg mask, anc copy -------------
__global__ void box_kernel(const float* __restrict__ anc_wh,
                           const float* __restrict__ grid,
                           const float* __restrict__ gt_cxys,
                           const float* __restrict__ gt_whs,
                           float* __restrict__ out) {
    const int idx = blockIdx.x * blockDim.x + threadIdx.x;   // B*NA*NG = 614400
    if (idx >= B_ * NA_ * NG_) return;
    const int g = idx % NG_;
    const int a = (idx / NG_) % NA_;
    const int b = idx / (NG_ * NA_);

    const int packed = g_asgn[b * NG_ + g];
    const int tgt = packed & 0xff;
    const int fg  = (packed >> 16) & 1;

    const float cx = gt_cxys[(b * N_ + tgt) * 2 + 0];
    const float cy = gt_cxys[(b * N_ + tgt) * 2 + 1];
    const float w  = gt_whs [(b * N_ + tgt) * 2 + 0];
    const float h  = gt_whs [(b * N_ + tgt) * 2 + 1];
    const float gx = grid[g * 2 + 0];
    const float gy = grid[g * 2 + 1];

    __stcs(reinterpret_cast<float4*>(out + BB_OFF) + idx,
           make_float4(cx - gx, cy - gy, w, h));

    const float aw = anc_wh[a * 2 + 0], ah = anc_wh[a * 2 + 1];
    const float r1 = w / aw, r2 = h / ah;
    const float m  = fmaxf(fmaxf(r1, 1.0f / r1), fmaxf(r2, 1.0f / r2));
    out[FG_OFF + idx] = (fg && (m < 4.0f)) ? 1.0f : 0.0f;

    if (idx < 6) out[ANC_OFF + idx] = anc_wh[idx];
}

// ------------- Kernel D: one-hot scores, one float4 per thread -------------
__global__ void score_kernel(float* __restrict__ out) {
    const long long idx = (long long)blockIdx.x * blockDim.x + threadIdx.x;
    const long long total = (long long)B_ * NA_ * NG_ * (NC_ / 4);     // 12,288,000
    if (idx >= total) return;

    const int c4 = (int)(idx % (NC_ / 4));
    const long long q = idx / (NC_ / 4);        // (b,a,g) flat
    const int g = (int)(q % NG_);
    const int b = (int)(q / (NG_ * NA_));

    const int lab = (g_asgn[b * NG_ + g] >> 8) & 0xff;
    const int c = c4 * 4;
    float4 v;
    v.x = (c + 0 == lab) ? 1.0f : 0.0f;
    v.y = (c + 1 == lab) ? 1.0f : 0.0f;
    v.z = (c + 2 == lab) ? 1.0f : 0.0f;
    v.w = (c + 3 == lab) ? 1.0f : 0.0f;
    __stcs(reinterpret_cast<float4*>(out + SC_OFF) + idx, v);
}

extern "C" void kernel_launch(void* const* d_in, const int* in_sizes, int n_in,
                              void* d_out, int out_size) {
    const float* anc_wh    = (const float*)d_in[0];
    const float* grid      = (const float*)d_in[1];
    const int*   gt_labels = (const int*)  d_in[2];
    const float* gt_cxys   = (const float*)d_in[3];
    const float* gt_whs    = (const float*)d_in[4];
    const float* mask_gt   = (const float*)d_in[5];
    float* out = (float*)d_out;

    topk_kernel<<<(B_ * N_ + 255) / 256, 256>>>(gt_cxys);
    assign_kernel<<<B_, 256>>>(gt_cxys, mask_gt, gt_labels);

    const int nbox = B_ * NA_ * NG_;
    box_kernel<<<(nbox + 255) / 256, 256>>>(anc_wh, grid, gt_cxys, gt_whs, out);

    const long long nsc = (long long)B_ * NA_ * NG_ * (NC_ / 4);
    score_kernel<<<(unsigned)((nsc + 255) / 256), 256>>>(out);
}